// round 13
// baseline (speedup 1.0000x reference)
#include <cuda_runtime.h>
#include <cstdint>

#define BATCH 8
#define DIM 32
#define NPTS 131072
#define KINST 64
#define IGNORE_IDX (-100)
#define W1 8          // warps per block in pass1
#define ROWS 65       // KINST + 1 trash row for invalid points
#define TPAD 36       // tile stride: 32+4, float4-aligned, conflict-free per quarter-warp
#define MUPAD 33      // mu stride in pass2 (scalar access, varying row)
#define APAD 32       // wsum stride: 16B-aligned rows, conflict-free
#define NT_B (NPTS / 32)     // 4096 tiles per batch
#define GRID1 304            // 8 batches * 38 blocks = 2 CTAs x 152 SMs
#define BPB (GRID1 / BATCH)  // 38 blocks per batch

// ---------------- global scratch (zero-initialized at load; self-cleaning) ----------
__device__ float        g_sums[BATCH][KINST][DIM];
__device__ float        g_cnt[BATCH][KINST];
__device__ float        g_lvar[BATCH];
__device__ float        g_res[BATCH][4];
__device__ unsigned int g_ticket[BATCH];   // monotonic across replays
__device__ unsigned int g_done;            // monotonic across replays

// ---------------- pass 1: per-cluster counts + sums, ALL batches ----------------
__global__ __launch_bounds__(256) void pass1_kernel(const float* __restrict__ emb,
                                                    const int*   __restrict__ sem,
                                                    const int*   __restrict__ ins) {
    extern __shared__ float sh[];
    const int w = threadIdx.x >> 5;
    const int l = threadIdx.x & 31;
    const int b   = blockIdx.x & (BATCH - 1);
    const int blk = blockIdx.x >> 3;

    float* wsum = sh + (size_t)w * (ROWS * APAD);                   // [65][32] per warp
    float* tile = sh + W1 * ROWS * APAD + (size_t)w * (32 * TPAD);  // [32][36] per warp
    float* cnts = sh + W1 * ROWS * APAD + W1 * 32 * TPAD;           // [W1][65]
    float* wcnt = cnts + (size_t)w * ROWS;

    for (int i = l; i < ROWS * APAD; i += 32) wsum[i] = 0.f;
    for (int i = l; i < ROWS;        i += 32) wcnt[i] = 0.f;

    const float* E = emb + (size_t)b * DIM * NPTS;
    const int*   S = sem + (size_t)b * NPTS;
    const int*   I = ins + (size_t)b * NPTS;

    const int sub = l >> 3;         // quarter-warp id
    const int m   = (l & 7) << 2;   // dim base for float4 path

    for (int t = blk * W1 + w; t < NT_B; t += BPB * W1) {
        const int n0 = t * 32;
        int cls = S[n0 + l];
        int id  = I[n0 + l];
        if (cls == 1)          id = 0;
        if (cls == IGNORE_IDX) id = KINST;

        unsigned mm = __match_any_sync(0xffffffffu, id);
        if ((mm & ((1u << l) - 1u)) == 0u) wcnt[id] += (float)__popc(mm);

        // fill tile: lane l holds point n0+l; buffer 4 dims in regs -> one STS.128
        #pragma unroll
        for (int s4 = 0; s4 < 8; s4++) {
            float r0 = E[(size_t)(s4 * 4 + 0) * NPTS + n0 + l];
            float r1 = E[(size_t)(s4 * 4 + 1) * NPTS + n0 + l];
            float r2 = E[(size_t)(s4 * 4 + 2) * NPTS + n0 + l];
            float r3 = E[(size_t)(s4 * 4 + 3) * NPTS + n0 + l];
            *(float4*)&tile[l * TPAD + s4 * 4] = make_float4(r0, r1, r2, r3);
        }
        __syncwarp();

        // accumulate 4 points/step: quarter-warp q owns row ip_q, float4 over dims.
        // Duplicate ids within the group -> scalar fallback (warp-uniform branch).
        #pragma unroll
        for (int g = 0; g < 8; g++) {
            const int p0 = g * 4;
            int ip0 = __shfl_sync(0xffffffffu, id, p0 + 0);
            int ip1 = __shfl_sync(0xffffffffu, id, p0 + 1);
            int ip2 = __shfl_sync(0xffffffffu, id, p0 + 2);
            int ip3 = __shfl_sync(0xffffffffu, id, p0 + 3);
            bool dup = (ip0 == ip1) | (ip0 == ip2) | (ip0 == ip3) |
                       (ip1 == ip2) | (ip1 == ip3) | (ip2 == ip3);
            if (!dup) {
                int row = (sub < 2) ? (sub == 0 ? ip0 : ip1)
                                    : (sub == 2 ? ip2 : ip3);
                float4 tv = *(const float4*)&tile[(p0 + sub) * TPAD + m];
                float* wp = &wsum[row * APAD + m];
                float4 wv = *(float4*)wp;
                wv.x += tv.x; wv.y += tv.y; wv.z += tv.z; wv.w += tv.w;
                *(float4*)wp = wv;
            } else {
                #pragma unroll
                for (int j = 0; j < 4; j++) {
                    int ip = (j < 2) ? (j == 0 ? ip0 : ip1)
                                     : (j == 2 ? ip2 : ip3);
                    wsum[ip * APAD + l] += tile[(p0 + j) * TPAD + l];
                }
            }
        }
        __syncwarp();
    }
    __syncthreads();

    // block-level reduction -> ONE atomic set per block
    if (threadIdx.x < KINST) {
        float c = 0.f;
        #pragma unroll
        for (int ww = 0; ww < W1; ww++)
            c += cnts[(size_t)ww * ROWS + threadIdx.x];
        atomicAdd(&g_cnt[b][threadIdx.x], c);
    }
    for (int r = w; r < KINST; r += W1) {
        float s = 0.f;
        #pragma unroll
        for (int ww = 0; ww < W1; ww++)
            s += sh[(size_t)ww * (ROWS * APAD) + r * APAD + l];
        atomicAdd(&g_sums[b][r][l], s);
    }
}

// ---------------- block reduce helper ----------------
__device__ __forceinline__ float block_reduce_256(float v, float* red8, float* bc) {
    const int tid = threadIdx.x;
    #pragma unroll
    for (int o = 16; o > 0; o >>= 1) v += __shfl_down_sync(0xffffffffu, v, o);
    if ((tid & 31) == 0) red8[tid >> 5] = v;
    __syncthreads();
    if (tid < 8) {
        float r = red8[tid];
        #pragma unroll
        for (int o = 4; o > 0; o >>= 1) r += __shfl_down_sync(0xffu, r, o);
        if (tid == 0) *bc = r;
    }
    __syncthreads();
    float res = *bc;
    __syncthreads();
    return res;
}

// ---------------- pass 2: hinged variance (float4) + fused finalize + self-clean ----
__global__ __launch_bounds__(256) void pass2_kernel(const float* __restrict__ emb,
                                                    const int*   __restrict__ sem,
                                                    const int*   __restrict__ ins,
                                                    float* __restrict__ out) {
    __shared__ float mu[KINST * MUPAD];
    __shared__ float invc[KINST];
    __shared__ float cs[KINST];
    __shared__ float red8[8];
    __shared__ float bc;
    __shared__ int   last_flag;
    const int tid = threadIdx.x;
    const int b   = blockIdx.x & (BATCH - 1);
    const int blk = blockIdx.x >> 3;

    for (int i = tid; i < KINST; i += blockDim.x) {
        float c = g_cnt[b][i];
        cs[i]   = c;
        invc[i] = 1.f / (c + 1e-8f);
    }
    __syncthreads();
    for (int i = tid; i < KINST * DIM; i += blockDim.x) {
        int k = i >> 5, d = i & 31;
        mu[k * MUPAD + d] = g_sums[b][k][d] * invc[k];
    }
    __syncthreads();

    const float* E = emb + (size_t)b * DIM * NPTS;
    const int*   S = sem + (size_t)b * NPTS;
    const int*   I = ins + (size_t)b * NPTS;

    float acc = 0.f;
    const int NQ = NPTS / 4;
    for (int q = blk * blockDim.x + tid; q < NQ; q += BPB * blockDim.x) {
        int4 c4 = ((const int4*)S)[q];
        int4 i4 = ((const int4*)I)[q];
        bool v0 = (c4.x != IGNORE_IDX), v1 = (c4.y != IGNORE_IDX);
        bool v2 = (c4.z != IGNORE_IDX), v3 = (c4.w != IGNORE_IDX);
        int id0 = (c4.x == 1) ? 0 : i4.x; if (!v0) id0 = 0;
        int id1 = (c4.y == 1) ? 0 : i4.y; if (!v1) id1 = 0;
        int id2 = (c4.z == 1) ? 0 : i4.z; if (!v2) id2 = 0;
        int id3 = (c4.w == 1) ? 0 : i4.w; if (!v3) id3 = 0;
        const float* m0 = &mu[id0 * MUPAD];
        const float* m1 = &mu[id1 * MUPAD];
        const float* m2 = &mu[id2 * MUPAD];
        const float* m3 = &mu[id3 * MUPAD];

        float s0 = 0.f, s1 = 0.f, s2 = 0.f, s3 = 0.f;
        #pragma unroll
        for (int d = 0; d < 32; d++) {
            float4 v = ((const float4*)(E + (size_t)d * NPTS))[q];
            s0 += fabsf(v.x - m0[d]);
            s1 += fabsf(v.y - m1[d]);
            s2 += fabsf(v.z - m2[d]);
            s3 += fabsf(v.w - m3[d]);
        }
        float h0 = fmaxf(s0 - 0.5f, 0.f);
        float h1 = fmaxf(s1 - 0.5f, 0.f);
        float h2 = fmaxf(s2 - 0.5f, 0.f);
        float h3 = fmaxf(s3 - 0.5f, 0.f);
        if (v0) acc += h0 * h0 * invc[id0];
        if (v1) acc += h1 * h1 * invc[id1];
        if (v2) acc += h2 * h2 * invc[id2];
        if (v3) acc += h3 * h3 * invc[id3];
    }

    // block reduce -> one atomic per block, then completion ticket (monotonic)
    float tot = block_reduce_256(acc, red8, &bc);
    if (tid == 0) {
        atomicAdd(&g_lvar[b], tot);
        __threadfence();
        unsigned prev = atomicAdd(&g_ticket[b], 1u);
        last_flag = ((prev % (unsigned)BPB) == (unsigned)(BPB - 1)) ? 1 : 0;
    }
    __syncthreads();
    if (!last_flag) return;
    __threadfence();  // acquire side: see all blocks' g_lvar adds

    // ---- fused finalize: only the last block of batch b ----
    float pr = 0.f, lreg = 0.f;
    for (int k = tid; k < KINST; k += blockDim.x) {
        if (cs[k] > 0.f) {
            pr += 1.f;
            float s = 0.f;
            #pragma unroll
            for (int d = 0; d < DIM; d++) s += fabsf(mu[k * MUPAD + d]);
            lreg += s;
        }
    }
    float hs = 0.f, np = 0.f;
    for (int pidx = tid; pidx < KINST * KINST; pidx += blockDim.x) {
        int i = pidx >> 6, j = pidx & 63;
        if (i != j && cs[i] > 0.f && cs[j] > 0.f) {
            float pd = 0.f;
            #pragma unroll
            for (int d = 0; d < DIM; d++)
                pd += fabsf(mu[i * MUPAD + d] - mu[j * MUPAD + d]);
            float h = fmaxf(3.0f - pd, 0.f);  // 2*DELTA_D - pdist
            hs += h * h;
            np += 1.f;
        }
    }

    float pr_t   = block_reduce_256(pr,   red8, &bc);
    float lreg_t = block_reduce_256(lreg, red8, &bc);
    float hs_t   = block_reduce_256(hs,   red8, &bc);
    float np_t   = block_reduce_256(np,   red8, &bc);

    // self-clean for next replay: every block already read g_sums/g_cnt (ticket-ordered)
    for (int i = tid; i < KINST * DIM; i += blockDim.x)
        ((float*)g_sums[b])[i] = 0.f;
    for (int i = tid; i < KINST; i += blockDim.x)
        g_cnt[b][i] = 0.f;

    if (tid == 0) {
        float lv     = atomicExch(&g_lvar[b], 0.f);   // read + reset
        float n_inst = fmaxf(pr_t, 1.f);
        float l_var  = lv / n_inst;
        float l_dist = (np_t > 0.f) ? hs_t / fmaxf(np_t, 1.f) : 0.f;
        float l_reg  = 0.001f * (lreg_t / n_inst);
        float loss   = l_var + l_dist + l_reg;
        g_res[b][0] = loss; g_res[b][1] = l_var;
        g_res[b][2] = l_dist; g_res[b][3] = l_reg;
        __threadfence();
        unsigned prev = atomicAdd(&g_done, 1u);
        if ((prev % (unsigned)BATCH) == (unsigned)(BATCH - 1)) {
            __threadfence();  // see all batches' g_res
            float o0 = 0.f, o1 = 0.f, o2 = 0.f, o3 = 0.f;
            #pragma unroll
            for (int bb = 0; bb < BATCH; bb++) {
                o0 += g_res[bb][0]; o1 += g_res[bb][1];
                o2 += g_res[bb][2]; o3 += g_res[bb][3];
            }
            const float inv_b = 1.f / (float)BATCH;
            out[0] = o0 * inv_b; out[1] = o1 * inv_b;
            out[2] = o2 * inv_b; out[3] = o3 * inv_b;
        }
    }
}

// ---------------- launch ----------------
extern "C" void kernel_launch(void* const* d_in, const int* in_sizes, int n_in,
                              void* d_out, int out_size) {
    const float* emb = (const float*)d_in[0];
    const int*   sem = (const int*)d_in[1];
    const int*   ins = (const int*)d_in[2];
    float*       out = (float*)d_out;

    const int SMEM1 = (W1 * ROWS * APAD + W1 * 32 * TPAD + W1 * ROWS) * 4;
    cudaFuncSetAttribute(pass1_kernel,
                         cudaFuncAttributeMaxDynamicSharedMemorySize, SMEM1);

    pass1_kernel<<<GRID1, 256, SMEM1>>>(emb, sem, ins);     // all batches, one wave
    pass2_kernel<<<GRID1, 256>>>(emb, sem, ins, out);       // variance + finalize + clean
}

// round 14
// speedup vs baseline: 1.4922x; 1.4922x over previous
#include <cuda_runtime.h>
#include <cstdint>

#define BATCH 8
#define DIM 32
#define NPTS 131072
#define KINST 64
#define IGNORE_IDX (-100)
#define W1 8          // warps per block in pass1
#define ROWS 65       // KINST + 1 trash row for invalid points
#define TPAD 36       // tile stride: 32+4 floats = 144B, 16B-aligned, conflict-free
#define MUPAD 33      // mu stride in pass2 (scalar access, varying row)
#define APAD 32       // wsum stride: row uniform across lanes -> conflict-free
#define NT_B (NPTS / 32)       // 4096 tiles per batch
#define GRID1 304              // pass1: 2 CTAs x 152 SMs (smem-capped)
#define BPB1 (GRID1 / BATCH)   // 38 pass1 blocks per batch
#define GRID2 608              // pass2: 4 CTAs x 152 SMs (latency-bound fix)
#define BPB2 (GRID2 / BATCH)   // 76 pass2 blocks per batch

// ---------------- global scratch (zero-initialized at load; self-cleaning) ----------
__device__ float        g_sums[BATCH][KINST][DIM];
__device__ float        g_cnt[BATCH][KINST];
__device__ float        g_lvar[BATCH];
__device__ float        g_res[BATCH][4];
__device__ unsigned int g_ticket[BATCH];   // monotonic across replays
__device__ unsigned int g_done;            // monotonic across replays

// ---------------- pass 1: per-cluster counts + sums, ALL batches ----------------
// Scalar transpose-scatter accumulate + software double-buffer: next tile's 32
// LDGs are in flight while the current tile's smem accumulate runs.
__global__ __launch_bounds__(256) void pass1_kernel(const float* __restrict__ emb,
                                                    const int*   __restrict__ sem,
                                                    const int*   __restrict__ ins) {
    extern __shared__ float sh[];
    const int w = threadIdx.x >> 5;
    const int l = threadIdx.x & 31;
    const int b   = blockIdx.x & (BATCH - 1);
    const int blk = blockIdx.x >> 3;

    float* wsum = sh + (size_t)w * (ROWS * APAD);                   // [65][32] per warp
    float* tile = sh + W1 * ROWS * APAD + (size_t)w * (32 * TPAD);  // [32][36] per warp
    float* cnts = sh + W1 * ROWS * APAD + W1 * 32 * TPAD;           // [W1][65]
    float* wcnt = cnts + (size_t)w * ROWS;

    for (int i = l; i < ROWS * APAD; i += 32) wsum[i] = 0.f;
    for (int i = l; i < ROWS;        i += 32) wcnt[i] = 0.f;

    const float* E = emb + (size_t)b * DIM * NPTS;
    const int*   S = sem + (size_t)b * NPTS;
    const int*   I = ins + (size_t)b * NPTS;

    const int STEP = BPB1 * W1;
    int t = blk * W1 + w;

    // prefetch tile t into registers
    float r[32];
    int   id = KINST;
    if (t < NT_B) {
        const int n0 = t * 32;
        int cls = S[n0 + l];
        id      = I[n0 + l];
        if (cls == 1)          id = 0;
        if (cls == IGNORE_IDX) id = KINST;
        #pragma unroll
        for (int s = 0; s < 32; s++)
            r[s] = E[(size_t)s * NPTS + n0 + l];
    }

    for (; t < NT_B; t += STEP) {
        const int curid = id;

        // per-point count, combined across equal ids within the warp
        unsigned mm = __match_any_sync(0xffffffffu, curid);
        if ((mm & ((1u << l) - 1u)) == 0u) wcnt[curid] += (float)__popc(mm);

        // commit prefetched tile to smem (8 x STS.128, conflict-free)
        #pragma unroll
        for (int s4 = 0; s4 < 8; s4++)
            *(float4*)&tile[l * TPAD + s4 * 4] =
                make_float4(r[4*s4], r[4*s4+1], r[4*s4+2], r[4*s4+3]);
        __syncwarp();

        // issue next tile's LDGs now -> latency overlaps the accumulate below
        const int t2 = t + STEP;
        if (t2 < NT_B) {
            const int n2 = t2 * 32;
            int cls = S[n2 + l];
            id      = I[n2 + l];
            if (cls == 1)          id = 0;
            if (cls == IGNORE_IDX) id = KINST;
            #pragma unroll
            for (int s = 0; s < 32; s++)
                r[s] = E[(size_t)s * NPTS + n2 + l];
        }

        // accumulate: serialize over points, lane l owns dim l (no atomics).
        // Row ip uniform across lanes -> stride-32 accumulator conflict-free.
        #pragma unroll
        for (int p = 0; p < 32; p++) {
            int ip = __shfl_sync(0xffffffffu, curid, p);
            wsum[ip * APAD + l] += tile[p * TPAD + l];
        }
        __syncwarp();
    }
    __syncthreads();

    // block-level reduction -> ONE atomic set per block
    if (threadIdx.x < KINST) {
        float c = 0.f;
        #pragma unroll
        for (int ww = 0; ww < W1; ww++)
            c += cnts[(size_t)ww * ROWS + threadIdx.x];
        atomicAdd(&g_cnt[b][threadIdx.x], c);
    }
    for (int rr = w; rr < KINST; rr += W1) {
        float s = 0.f;
        #pragma unroll
        for (int ww = 0; ww < W1; ww++)
            s += sh[(size_t)ww * (ROWS * APAD) + rr * APAD + l];
        atomicAdd(&g_sums[b][rr][l], s);
    }
}

// ---------------- block reduce helper ----------------
__device__ __forceinline__ float block_reduce_256(float v, float* red8, float* bc) {
    const int tid = threadIdx.x;
    #pragma unroll
    for (int o = 16; o > 0; o >>= 1) v += __shfl_down_sync(0xffffffffu, v, o);
    if ((tid & 31) == 0) red8[tid >> 5] = v;
    __syncthreads();
    if (tid < 8) {
        float r = red8[tid];
        #pragma unroll
        for (int o = 4; o > 0; o >>= 1) r += __shfl_down_sync(0xffu, r, o);
        if (tid == 0) *bc = r;
    }
    __syncthreads();
    float res = *bc;
    __syncthreads();
    return res;
}

// ---------------- pass 2: hinged variance (float4) + fused finalize + self-clean ----
__global__ __launch_bounds__(256) void pass2_kernel(const float* __restrict__ emb,
                                                    const int*   __restrict__ sem,
                                                    const int*   __restrict__ ins,
                                                    float* __restrict__ out) {
    __shared__ float mu[KINST * MUPAD];
    __shared__ float invc[KINST];
    __shared__ float cs[KINST];
    __shared__ float red8[8];
    __shared__ float bc;
    __shared__ int   last_flag;
    const int tid = threadIdx.x;
    const int b   = blockIdx.x & (BATCH - 1);
    const int blk = blockIdx.x >> 3;

    for (int i = tid; i < KINST; i += blockDim.x) {
        float c = g_cnt[b][i];
        cs[i]   = c;
        invc[i] = 1.f / (c + 1e-8f);
    }
    __syncthreads();
    for (int i = tid; i < KINST * DIM; i += blockDim.x) {
        int k = i >> 5, d = i & 31;
        mu[k * MUPAD + d] = g_sums[b][k][d] * invc[k];
    }
    __syncthreads();

    const float* E = emb + (size_t)b * DIM * NPTS;
    const int*   S = sem + (size_t)b * NPTS;
    const int*   I = ins + (size_t)b * NPTS;

    float acc = 0.f;
    const int NQ = NPTS / 4;
    for (int q = blk * blockDim.x + tid; q < NQ; q += BPB2 * blockDim.x) {
        int4 c4 = ((const int4*)S)[q];
        int4 i4 = ((const int4*)I)[q];
        bool v0 = (c4.x != IGNORE_IDX), v1 = (c4.y != IGNORE_IDX);
        bool v2 = (c4.z != IGNORE_IDX), v3 = (c4.w != IGNORE_IDX);
        int id0 = (c4.x == 1) ? 0 : i4.x; if (!v0) id0 = 0;
        int id1 = (c4.y == 1) ? 0 : i4.y; if (!v1) id1 = 0;
        int id2 = (c4.z == 1) ? 0 : i4.z; if (!v2) id2 = 0;
        int id3 = (c4.w == 1) ? 0 : i4.w; if (!v3) id3 = 0;
        const float* m0 = &mu[id0 * MUPAD];
        const float* m1 = &mu[id1 * MUPAD];
        const float* m2 = &mu[id2 * MUPAD];
        const float* m3 = &mu[id3 * MUPAD];

        float s0 = 0.f, s1 = 0.f, s2 = 0.f, s3 = 0.f;
        #pragma unroll
        for (int d = 0; d < 32; d++) {
            float4 v = ((const float4*)(E + (size_t)d * NPTS))[q];
            s0 += fabsf(v.x - m0[d]);
            s1 += fabsf(v.y - m1[d]);
            s2 += fabsf(v.z - m2[d]);
            s3 += fabsf(v.w - m3[d]);
        }
        float h0 = fmaxf(s0 - 0.5f, 0.f);
        float h1 = fmaxf(s1 - 0.5f, 0.f);
        float h2 = fmaxf(s2 - 0.5f, 0.f);
        float h3 = fmaxf(s3 - 0.5f, 0.f);
        if (v0) acc += h0 * h0 * invc[id0];
        if (v1) acc += h1 * h1 * invc[id1];
        if (v2) acc += h2 * h2 * invc[id2];
        if (v3) acc += h3 * h3 * invc[id3];
    }

    // block reduce -> one atomic per block, then completion ticket (monotonic)
    float tot = block_reduce_256(acc, red8, &bc);
    if (tid == 0) {
        atomicAdd(&g_lvar[b], tot);
        __threadfence();
        unsigned prev = atomicAdd(&g_ticket[b], 1u);
        last_flag = ((prev % (unsigned)BPB2) == (unsigned)(BPB2 - 1)) ? 1 : 0;
    }
    __syncthreads();
    if (!last_flag) return;
    __threadfence();  // acquire side: see all blocks' g_lvar adds

    // ---- fused finalize: only the last block of batch b ----
    float pr = 0.f, lreg = 0.f;
    for (int k = tid; k < KINST; k += blockDim.x) {
        if (cs[k] > 0.f) {
            pr += 1.f;
            float s = 0.f;
            #pragma unroll
            for (int d = 0; d < DIM; d++) s += fabsf(mu[k * MUPAD + d]);
            lreg += s;
        }
    }
    float hs = 0.f, np = 0.f;
    for (int pidx = tid; pidx < KINST * KINST; pidx += blockDim.x) {
        int i = pidx >> 6, j = pidx & 63;
        if (i != j && cs[i] > 0.f && cs[j] > 0.f) {
            float pd = 0.f;
            #pragma unroll
            for (int d = 0; d < DIM; d++)
                pd += fabsf(mu[i * MUPAD + d] - mu[j * MUPAD + d]);
            float h = fmaxf(3.0f - pd, 0.f);  // 2*DELTA_D - pdist
            hs += h * h;
            np += 1.f;
        }
    }

    float pr_t   = block_reduce_256(pr,   red8, &bc);
    float lreg_t = block_reduce_256(lreg, red8, &bc);
    float hs_t   = block_reduce_256(hs,   red8, &bc);
    float np_t   = block_reduce_256(np,   red8, &bc);

    // self-clean for next replay (all blocks of batch b already read these)
    for (int i = tid; i < KINST * DIM; i += blockDim.x)
        ((float*)g_sums[b])[i] = 0.f;
    for (int i = tid; i < KINST; i += blockDim.x)
        g_cnt[b][i] = 0.f;

    if (tid == 0) {
        float lv     = atomicExch(&g_lvar[b], 0.f);   // read + reset
        float n_inst = fmaxf(pr_t, 1.f);
        float l_var  = lv / n_inst;
        float l_dist = (np_t > 0.f) ? hs_t / fmaxf(np_t, 1.f) : 0.f;
        float l_reg  = 0.001f * (lreg_t / n_inst);
        float loss   = l_var + l_dist + l_reg;
        g_res[b][0] = loss; g_res[b][1] = l_var;
        g_res[b][2] = l_dist; g_res[b][3] = l_reg;
        __threadfence();
        unsigned prev = atomicAdd(&g_done, 1u);
        if ((prev % (unsigned)BATCH) == (unsigned)(BATCH - 1)) {
            __threadfence();  // see all batches' g_res
            float o0 = 0.f, o1 = 0.f, o2 = 0.f, o3 = 0.f;
            #pragma unroll
            for (int bb = 0; bb < BATCH; bb++) {
                o0 += g_res[bb][0]; o1 += g_res[bb][1];
                o2 += g_res[bb][2]; o3 += g_res[bb][3];
            }
            const float inv_b = 1.f / (float)BATCH;
            out[0] = o0 * inv_b; out[1] = o1 * inv_b;
            out[2] = o2 * inv_b; out[3] = o3 * inv_b;
        }
    }
}

// ---------------- launch ----------------
extern "C" void kernel_launch(void* const* d_in, const int* in_sizes, int n_in,
                              void* d_out, int out_size) {
    const float* emb = (const float*)d_in[0];
    const int*   sem = (const int*)d_in[1];
    const int*   ins = (const int*)d_in[2];
    float*       out = (float*)d_out;

    const int SMEM1 = (W1 * ROWS * APAD + W1 * 32 * TPAD + W1 * ROWS) * 4;
    cudaFuncSetAttribute(pass1_kernel,
                         cudaFuncAttributeMaxDynamicSharedMemorySize, SMEM1);

    pass1_kernel<<<GRID1, 256, SMEM1>>>(emb, sem, ins);     // all batches, one wave
    pass2_kernel<<<GRID2, 256>>>(emb, sem, ins, out);       // variance + finalize + clean
}